// round 7
// baseline (speedup 1.0000x reference)
#include <cuda_runtime.h>
#include <cstdint>

// 3-level db4 wavedec (periodization) along axis 1 of (64, 4096, 64) fp32.
// Output rows: [cA3 (512) | cD3 (512) | cD2 (1024) | cD1 (2048)] x 64 feats.
//
// R7: the per-tile x window (170 contiguous rows = 43.5 KB) is staged into
// shared memory with ONE cp.async.bulk per block (mbarrier completion),
// eliminating all per-thread global-load latency from the critical path.
// Compute (packed f32x2 FMA, 128-bit LDS/STG) then runs entirely out of smem.

#define NTHREADS  256

#define A1_ROWS   82
#define A2_ROWS   38

#define XS_BYTES  (170 * 256)          // 43520: x window
#define A1_BYTES  (86  * 256)          // 22016: cA1 rows 0..85 (84,85 garbage-ok)
#define A2_BYTES  (40  * 256)          // 10240
#define OFF_X     0
#define OFF_A1    (OFF_X  + XS_BYTES)  // 43520
#define OFF_A2    (OFF_A1 + A1_BYTES)  // 65536
#define OFF_MBAR  (OFF_A2 + A2_BYTES)  // 75776
#define SMEM_BYTES (OFF_MBAR + 16)     // 75792 -> 3 CTAs/SM

__device__ __forceinline__ void fma2(unsigned long long& acc,
                                     unsigned long long w,
                                     unsigned long long c) {
    asm("fma.rn.f32x2 %0, %1, %2, %0;" : "+l"(acc) : "l"(w), "l"(c));
}

__device__ __forceinline__ unsigned long long pneg(unsigned long long v) {
    return v ^ 0x8000000080000000ull;
}

__device__ __forceinline__ uint32_t smem_u32(const void* p) {
    uint32_t a;
    asm("{ .reg .u64 t; cvta.to.shared.u64 t, %1; cvt.u32.u64 %0, t; }"
        : "=r"(a) : "l"(p));
    return a;
}

__device__ __forceinline__ void bulk_g2s(uint32_t dst, const void* src,
                                         uint32_t bytes, uint32_t mbar) {
    asm volatile(
        "cp.async.bulk.shared::cluster.global.mbarrier::complete_tx::bytes "
        "[%0], [%1], %2, [%3];"
        :: "r"(dst), "l"(src), "r"(bytes), "r"(mbar) : "memory");
}

__device__ __forceinline__ void mbar_wait0(uint32_t mbar) {
    asm volatile(
        "{\n\t"
        ".reg .pred P;\n\t"
        "W_%=:\n\t"
        "mbarrier.try_wait.parity.acquire.cta.shared::cta.b64 P, [%0], 0, 0x989680;\n\t"
        "@P bra D_%=;\n\t"
        "bra W_%=;\n\t"
        "D_%=:\n\t"
        "}"
        :: "r"(mbar) : "memory");
}

// consume batched window v[14] into 4-row accumulators:
// a[q] += v[2q+t]*RLO[t];  d[q] += s(t)*v[2q+t]*RLO[7-t]
#define CONSUME_WINDOW                                              \
    _Pragma("unroll")                                               \
    for (int t = 0; t < 14; ++t) {                                  \
        const unsigned long long WL = v[t].x, WH = v[t].y;          \
        const unsigned long long nWL = (t & 1) ? pneg(WL) : WL;     \
        const unsigned long long nWH = (t & 1) ? pneg(WH) : WH;     \
        _Pragma("unroll")                                           \
        for (int q = 0; q < 4; ++q) {                               \
            const int tt = t - 2 * q;                               \
            if (tt >= 0 && tt < 8) {                                \
                fma2(aL[q], WL, clo[tt]);                           \
                fma2(aH[q], WH, clo[tt]);                           \
                fma2(dL[q], nWL, clo[7 - tt]);                      \
                fma2(dH[q], nWH, clo[7 - tt]);                      \
            }                                                       \
        }                                                           \
    }

__global__ void __launch_bounds__(NTHREADS, 3)
wavedec_kernel(const float* __restrict__ x, float* __restrict__ out) {
    extern __shared__ char smem[];
    ulonglong2* s_x  = reinterpret_cast<ulonglong2*>(smem + OFF_X);
    ulonglong2* s_a1 = reinterpret_cast<ulonglong2*>(smem + OFF_A1);
    ulonglong2* s_a2 = reinterpret_cast<ulonglong2*>(smem + OFF_A2);
    const uint32_t mbar = smem_u32(smem + OFF_MBAR);

    const int tid  = threadIdx.x;
    const int f4   = tid & 15;    // float4 feature lane (64 floats = 16 float4)
    const int grp  = tid >> 4;    // 0..15, each group: 4 consecutive rows/pass
    const int tile = blockIdx.x;  // 0..31
    const int b    = blockIdx.y;  // 0..63

    const float* __restrict__ xb = x + (size_t)b * 4096 * 64;
    ulonglong2* __restrict__ ob4 =
        reinterpret_cast<ulonglong2*>(out + (size_t)b * 4096 * 64);

    // ---- Stage the x window (rows g0..g0+169, g0 = 128*tile - 42) ----
    if (tid == 0) {
        asm volatile(
            "mbarrier.init.shared.b64 [%0], 1;\n\t"
            "fence.mbarrier_init.release.cluster;"
            :: "r"(mbar) : "memory");
        asm volatile("mbarrier.arrive.expect_tx.shared.b64 _, [%0], %1;"
                     :: "r"(mbar), "r"((uint32_t)XS_BYTES) : "memory");
        const uint32_t sx = smem_u32(smem + OFF_X);
        if (tile == 0) {
            // rows 4054..4095 then 0..127
            bulk_g2s(sx,         xb + (size_t)4054 * 64, 42 * 256, mbar);
            bulk_g2s(sx + 42*256, xb,                    128 * 256, mbar);
        } else {
            bulk_g2s(sx, xb + (size_t)(128 * tile - 42) * 64, XS_BYTES, mbar);
        }
    }

    // Reversed approx filter: out_a[i] = sum_t src[2i+t] * RLO[t]
    const float RLO[8] = {
         0.23037781330885523f,  0.7148465705525415f,   0.6308807679295904f,
        -0.02798376941698385f, -0.18703481171888114f,  0.030841381835986965f,
         0.032883011666982945f, -0.010597401784997278f };
    unsigned long long clo[8];
#pragma unroll
    for (int t = 0; t < 8; ++t)
        clo[t] = (unsigned long long)__float_as_uint(RLO[t]) * 0x100000001ull;

    __syncthreads();         // mbar init visible before anyone waits
    mbar_wait0(mbar);        // x window resident

    // ---- Level 1: s_x -> cA1 (smem) + cD1 (global) ----
    // (reads for the 2 trailing garbage rows spill past s_x into s_a1;
    //  in-bounds of the allocation, results discarded)
#pragma unroll
    for (int pass = 0; pass < 2; ++pass) {
        const int i0 = pass * 64 + grp * 4;
        if (i0 < A1_ROWS) {
            unsigned long long aL[4] = {}, aH[4] = {}, dL[4] = {}, dH[4] = {};
            ulonglong2 v[14];
            const ulonglong2* p = s_x + (size_t)(2 * i0) * 16 + f4;
#pragma unroll
            for (int t = 0; t < 14; ++t)
                v[t] = p[t * 16];
            CONSUME_WINDOW
#pragma unroll
            for (int q = 0; q < 4; ++q) {
                const int i = i0 + q;          // max 83 < 86
                s_a1[i * 16 + f4] = make_ulonglong2(aL[q], aH[q]);
                if (i >= 18 && i < A1_ROWS)
                    ob4[(size_t)(2048 + 64 * tile + (i - 18)) * 16 + f4] =
                        make_ulonglong2(dL[q], dH[q]);
            }
        }
    }
    __syncthreads();

    // ---- Level 2: cA1 (smem) -> cA2 (smem) + cD2 (global) ----
    {
        const int i0 = grp * 4;
        if (i0 < A2_ROWS) {
            unsigned long long aL[4] = {}, aH[4] = {}, dL[4] = {}, dH[4] = {};
            ulonglong2 v[14];
            const ulonglong2* p = s_a1 + (size_t)(2 * i0) * 16 + f4;
#pragma unroll
            for (int t = 0; t < 14; ++t)
                v[t] = p[t * 16];
            CONSUME_WINDOW
#pragma unroll
            for (int q = 0; q < 4; ++q) {
                const int i = i0 + q;          // max 39 < 40
                s_a2[i * 16 + f4] = make_ulonglong2(aL[q], aH[q]);
                if (i >= 6 && i < A2_ROWS)
                    ob4[(size_t)(1024 + 32 * tile + (i - 6)) * 16 + f4] =
                        make_ulonglong2(dL[q], dH[q]);
            }
        }
    }
    __syncthreads();

    // ---- Level 3: cA2 (smem) -> cA3 + cD3 (global) ----
    {
        const int i0 = grp * 4;
        if (i0 < 16) {
            unsigned long long aL[4] = {}, aH[4] = {}, dL[4] = {}, dH[4] = {};
            ulonglong2 v[14];
            const ulonglong2* p = s_a2 + (size_t)(2 * i0) * 16 + f4;
#pragma unroll
            for (int t = 0; t < 14; ++t)
                v[t] = p[t * 16];
            CONSUME_WINDOW
#pragma unroll
            for (int q = 0; q < 4; ++q) {
                const int i = i0 + q;
                ob4[(size_t)(16 * tile + i) * 16 + f4] =
                    make_ulonglong2(aL[q], aH[q]);
                ob4[(size_t)(512 + 16 * tile + i) * 16 + f4] =
                    make_ulonglong2(dL[q], dH[q]);
            }
        }
    }
}

extern "C" void kernel_launch(void* const* d_in, const int* in_sizes, int n_in,
                              void* d_out, int out_size) {
    const float* x = (const float*)d_in[0];
    float* out = (float*)d_out;

    cudaFuncSetAttribute(wavedec_kernel,
                         cudaFuncAttributeMaxDynamicSharedMemorySize, SMEM_BYTES);

    dim3 grid(32, 64);
    wavedec_kernel<<<grid, NTHREADS, SMEM_BYTES>>>(x, out);
}